// round 2
// baseline (speedup 1.0000x reference)
#include <cuda_runtime.h>
#include <math.h>

#define BATCH 16
#define NPTS  2048
#define KNN   10

__device__ float g_loss[BATCH * NPTS];
__device__ unsigned int g_min[BATCH];   // float bits; positive floats => int-min == float-min

__device__ __forceinline__ void sort3(float& a, float& b, float& c) {
    float lo = fminf(a, b), hi = fmaxf(a, b);
    float l0 = fminf(lo, c);
    float l2 = fmaxf(hi, c);
    float l1 = fmaxf(lo, fminf(hi, c));
    a = l0; b = l1; c = l2;
}

__global__ void init_min_kernel() {
    if (threadIdx.x < BATCH) g_min[threadIdx.x] = 0x7f800000u;  // +inf
}

__global__ __launch_bounds__(256) void knn_loss_kernel(const float* __restrict__ src,
                                                       const float* __restrict__ tgt) {
    extern __shared__ float4 sm4[];
    float4* s4 = sm4;              // [NPTS] : x, y, z, |p|^2
    float4* t4 = sm4 + NPTS;       // [NPTS] : tx, ty, tz, unused

    const int b     = blockIdx.x >> 3;
    const int chunk = blockIdx.x & 7;
    const int tid   = threadIdx.x;

    const float* sb = src + b * 3 * NPTS;
    const float* tb = tgt + b * 3 * NPTS;
    for (int i = tid; i < NPTS; i += 256) {
        float x = sb[i], y = sb[NPTS + i], z = sb[2 * NPTS + i];
        s4[i] = make_float4(x, y, z, x * x + y * y + z * z);   // matches jnp.sum(xt*xt,-1)
        t4[i] = make_float4(tb[i], tb[NPTS + i], tb[2 * NPTS + i], 0.0f);
    }
    __syncthreads();

    const float FINF = __int_as_float(0x7f800000);
    const int n = chunk * 256 + tid;

    const float4 pn = s4[n];
    const float xn = pn.x, yn = pn.y, zn = pn.z, sqn = pn.w;

    // ---- Phase 1: top-10 smallest key = d2 + 1e-7 with key >= 0.1 (ref's masking).
    // Ascending scan + strict-< insertion reproduces top_k's lower-index tie-break.
    float kb[KNN];
    int   ib[KNN];
#pragma unroll
    for (int i = 0; i < KNN; i++) { kb[i] = FINF; ib[i] = 0; }
    float thresh = FINF;

    for (int m0 = 0; m0 < NPTS; m0 += 8) {
        float key[8];
#pragma unroll
        for (int u = 0; u < 8; u++) {
            float4 c = s4[m0 + u];
            float dot = xn * c.x + yn * c.y + zn * c.z;
            float d2  = (sqn + c.w) - 2.0f * dot;   // ref: sq_n + sq_m - 2*einsum
            key[u] = d2 + 1e-7f;                    // ref: distance = -(d2+1e-7)
        }
#pragma unroll
        for (int u = 0; u < 8; u++) {
            if (key[u] < thresh) {                  // rare path after warm-up
                if (key[u] >= 0.1f) {               // excluded iff distance > -0.1
                    kb[KNN - 1] = key[u]; ib[KNN - 1] = m0 + u;
#pragma unroll
                    for (int s = KNN - 1; s > 0; --s) {
                        if (kb[s] < kb[s - 1]) {
                            float tk = kb[s]; kb[s] = kb[s - 1]; kb[s - 1] = tk;
                            int   ti = ib[s]; ib[s] = ib[s - 1]; ib[s - 1] = ti;
                        } else break;
                    }
                    thresh = kb[KNN - 1];
                }
            }
        }
    }

    // ---- Phase 2: gather 10 neighbors (src & tgt) into registers
    float nsx[KNN], nsy[KNN], nsz[KNN], ntx[KNN], nty[KNN], ntz[KNN];
#pragma unroll
    for (int i = 0; i < KNN; i++) {
        float4 cs = s4[ib[i]];
        float4 ct = t4[ib[i]];
        nsx[i] = cs.x; nsy[i] = cs.y; nsz[i] = cs.z;
        ntx[i] = ct.x; nty[i] = ct.y; ntz[i] = ct.z;
    }
    const float4 tn = t4[n];
    const float xtn = tn.x, ytn = tn.y, ztn = tn.z;

    // self->neighbor squared distances (direct diff form, as in get_tri)
    float ds0[KNN], dt0[KNN];
#pragma unroll
    for (int i = 0; i < KNN; i++) {
        float dx = xn - nsx[i], dy = yn - nsy[i], dz = zn - nsz[i];
        ds0[i] = dx * dx + dy * dy + dz * dz;
        float ex = xtn - ntx[i], ey = ytn - nty[i], ez = ztn - ntz[i];
        dt0[i] = ex * ex + ey * ey + ez * ez;
    }

    // ---- Phase 3: 45 pairs; keep 10 smallest losses (multiset -> tie-break free)
    float lb[KNN];
#pragma unroll
    for (int i = 0; i < KNN; i++) lb[i] = FINF;

#pragma unroll
    for (int i = 0; i < KNN; i++) {
#pragma unroll
        for (int j = i + 1; j < KNN; j++) {
            float dx = nsx[i] - nsx[j], dy = nsy[i] - nsy[j], dz = nsz[i] - nsz[j];
            float bs = dx * dx + dy * dy + dz * dz;
            float l0 = ds0[i], l1 = bs, l2 = ds0[j];
            sort3(l0, l1, l2);

            float ex = ntx[i] - ntx[j], ey = nty[i] - nty[j], ez = ntz[i] - ntz[j];
            float bt = ex * ex + ey * ey + ez * ez;
            float m0 = dt0[i], m1 = bt, m2 = dt0[j];
            sort3(m0, m1, m2);
            m0 += 1e-6f; m1 += 1e-6f; m2 += 1e-6f;   // length_tgt = sort(tri) + EPS

            float e0 = l0 - m0, e1 = l1 - m1, e2 = l2 - m2;
            float num = e0 * e0 + e1 * e1 + e2 * e2;
            float s0 = l0 + m0, s1 = l1 + m1, s2 = l2 + m2;
            float den = s0 * s0 + s1 * s1 + s2 * s2;
            float loss = num / den;

            if (loss < lb[KNN - 1]) {
                lb[KNN - 1] = loss;
#pragma unroll
                for (int s = KNN - 1; s > 0; --s) {
                    if (lb[s] < lb[s - 1]) {
                        float t = lb[s]; lb[s] = lb[s - 1]; lb[s - 1] = t;
                    } else break;
                }
            }
        }
    }

    float acc = 0.0f;
#pragma unroll
    for (int i = 0; i < KNN; i++) acc += sqrtf(lb[i] + 1e-6f);
    float mloss = acc / 10.0f;

    g_loss[b * NPTS + n] = mloss;

    // ---- block min -> atomicMin on float bits (all values > 0)
    float v = mloss;
#pragma unroll
    for (int o = 16; o > 0; o >>= 1) v = fminf(v, __shfl_xor_sync(0xffffffffu, v, o));
    __shared__ float wmin[8];
    if ((tid & 31) == 0) wmin[tid >> 5] = v;
    __syncthreads();
    if (tid == 0) {
        float bm = wmin[0];
#pragma unroll
        for (int w = 1; w < 8; w++) bm = fminf(bm, wmin[w]);
        atomicMin(&g_min[b], (unsigned int)__float_as_int(bm));
    }
}

__global__ __launch_bounds__(256) void weight_kernel(float* __restrict__ out) {
    const int b = blockIdx.x >> 3;
    const int i = (blockIdx.x & 7) * 256 + threadIdx.x;
    const float minl = __int_as_float((int)g_min[b]);
    float t = g_loss[b * NPTS + i] - minl;
    float w = 2.0f / (1.0f + expf(30.0f * t));   // 2*sigmoid(-30*t)
    out[b * NPTS + i] = (w > 0.6f) ? 1.0f : 0.0f;
}

extern "C" void kernel_launch(void* const* d_in, const int* in_sizes, int n_in,
                              void* d_out, int out_size) {
    const float* src = (const float*)d_in[0];
    const float* tgt = (const float*)d_in[1];
    float* out = (float*)d_out;

    const int smem = 2 * NPTS * (int)sizeof(float4);   // 64 KB
    cudaFuncSetAttribute(knn_loss_kernel, cudaFuncAttributeMaxDynamicSharedMemorySize, smem);

    init_min_kernel<<<1, 32>>>();
    knn_loss_kernel<<<BATCH * 8, 256, smem>>>(src, tgt);
    weight_kernel<<<BATCH * 8, 256>>>(out);
}

// round 4
// speedup vs baseline: 1.6706x; 1.6706x over previous
#include <cuda_runtime.h>
#include <math.h>

#define BATCH 16
#define NPTS  2048
#define KNN   10

__device__ float g_loss[BATCH * NPTS];
__device__ unsigned int g_min[BATCH];   // float bits; positive floats => int-min == float-min

__device__ __forceinline__ void sort3(float& a, float& b, float& c) {
    float lo = fminf(a, b), hi = fmaxf(a, b);
    float l0 = fminf(lo, c);
    float l2 = fmaxf(hi, c);
    float l1 = fmaxf(lo, fminf(hi, c));
    a = l0; b = l1; c = l2;
}

__global__ void init_min_kernel() {
    if (threadIdx.x < BATCH) g_min[threadIdx.x] = 0x7f800000u;  // +inf
}

__global__ void dummy_kernel() {}   // padding so ncu (-s 5) captures knn_loss_kernel

__global__ __launch_bounds__(256) void knn_loss_kernel(const float* __restrict__ src,
                                                       const float* __restrict__ tgt) {
    extern __shared__ float4 sm4[];
    float4* s4 = sm4;              // [NPTS] : x, y, z, |p|^2
    float4* t4 = sm4 + NPTS;       // [NPTS] : tx, ty, tz, unused

    const int b     = blockIdx.x >> 3;
    const int chunk = blockIdx.x & 7;
    const int tid   = threadIdx.x;

    const float* sb = src + b * 3 * NPTS;
    const float* tb = tgt + b * 3 * NPTS;
    for (int i = tid; i < NPTS; i += 256) {
        float x = sb[i], y = sb[NPTS + i], z = sb[2 * NPTS + i];
        s4[i] = make_float4(x, y, z, x * x + y * y + z * z);   // matches jnp.sum(xt*xt,-1)
        t4[i] = make_float4(tb[i], tb[NPTS + i], tb[2 * NPTS + i], 0.0f);
    }
    __syncthreads();

    const float FINF = __int_as_float(0x7f800000);
    const int n = chunk * 256 + tid;

    const float4 pn = s4[n];
    const float xn = pn.x, yn = pn.y, zn = pn.z, sqn = pn.w;

    // ---- Phase 1: top-10 smallest key = d2 + 1e-7 with key >= 0.1 (ref's masking).
    // Single flat branch; branchless 10-stage predicated shift inside (no BSSY chains).
    // Strict-< keeps earlier (lower-index) entries on ties == top_k tie-break at the
    // selection boundary; order WITHIN the kept set is irrelevant (triangle multiset).
    float kb[KNN];
    int   ib[KNN];
#pragma unroll
    for (int i = 0; i < KNN; i++) { kb[i] = FINF; ib[i] = 0; }
    float thresh = FINF;

    for (int m0 = 0; m0 < NPTS; m0 += 8) {
        float key[8];
#pragma unroll
        for (int u = 0; u < 8; u++) {
            float4 c = s4[m0 + u];
            float dot = xn * c.x + yn * c.y + zn * c.z;
            float d2  = (sqn + c.w) - 2.0f * dot;   // ref: sq_n + sq_m - 2*einsum
            key[u] = d2 + 1e-7f;                    // ref: distance = -(d2+1e-7)
        }
#pragma unroll
        for (int u = 0; u < 8; u++) {
            if (key[u] < thresh && key[u] >= 0.1f) {   // rare after warm-up
                float ck = key[u];
                int   ci = m0 + u;
#pragma unroll
                for (int s = 0; s < KNN; s++) {
                    bool  lt = ck < kb[s];
                    float nk = lt ? kb[s] : ck;
                    int   ni = lt ? ib[s] : ci;
                    kb[s] = lt ? ck : kb[s];
                    ib[s] = lt ? ci : ib[s];
                    ck = nk; ci = ni;
                }
                thresh = kb[KNN - 1];
            }
        }
    }

    // ---- Phase 2: gather 10 neighbors (src & tgt) into registers
    float nsx[KNN], nsy[KNN], nsz[KNN], ntx[KNN], nty[KNN], ntz[KNN];
#pragma unroll
    for (int i = 0; i < KNN; i++) {
        float4 cs = s4[ib[i]];
        float4 ct = t4[ib[i]];
        nsx[i] = cs.x; nsy[i] = cs.y; nsz[i] = cs.z;
        ntx[i] = ct.x; nty[i] = ct.y; ntz[i] = ct.z;
    }
    const float4 tn = t4[n];
    const float xtn = tn.x, ytn = tn.y, ztn = tn.z;

    // self->neighbor squared distances (direct diff form, as in get_tri)
    float ds0[KNN], dt0[KNN];
#pragma unroll
    for (int i = 0; i < KNN; i++) {
        float dx = xn - nsx[i], dy = yn - nsy[i], dz = zn - nsz[i];
        ds0[i] = dx * dx + dy * dy + dz * dz;
        float ex = xtn - ntx[i], ey = ytn - nty[i], ez = ztn - ntz[i];
        dt0[i] = ex * ex + ey * ey + ez * ez;
    }

    // ---- Phase 3: 45 pairs; keep 10 smallest losses.
    // Fully branchless min/max bubble insert (multiset of losses -> order-free).
    float lb[KNN];
#pragma unroll
    for (int i = 0; i < KNN; i++) lb[i] = FINF;

#pragma unroll
    for (int i = 0; i < KNN; i++) {
#pragma unroll
        for (int j = i + 1; j < KNN; j++) {
            float dx = nsx[i] - nsx[j], dy = nsy[i] - nsy[j], dz = nsz[i] - nsz[j];
            float bs = dx * dx + dy * dy + dz * dz;
            float l0 = ds0[i], l1 = bs, l2 = ds0[j];
            sort3(l0, l1, l2);

            float ex = ntx[i] - ntx[j], ey = nty[i] - nty[j], ez = ntz[i] - ntz[j];
            float bt = ex * ex + ey * ey + ez * ez;
            float m0 = dt0[i], m1 = bt, m2 = dt0[j];
            sort3(m0, m1, m2);
            m0 += 1e-6f; m1 += 1e-6f; m2 += 1e-6f;   // length_tgt = sort(tri) + EPS

            float e0 = l0 - m0, e1 = l1 - m1, e2 = l2 - m2;
            float num = e0 * e0 + e1 * e1 + e2 * e2;
            float s0 = l0 + m0, s1 = l1 + m1, s2 = l2 + m2;
            float den = s0 * s0 + s1 * s1 + s2 * s2;
            float ck = num / den;

#pragma unroll
            for (int s = 0; s < KNN; s++) {           // branchless bubble insert
                float mn = fminf(ck, lb[s]);
                ck = fmaxf(ck, lb[s]);
                lb[s] = mn;
            }
        }
    }

    float acc = 0.0f;
#pragma unroll
    for (int i = 0; i < KNN; i++) acc += sqrtf(lb[i] + 1e-6f);
    float mloss = acc / 10.0f;

    g_loss[b * NPTS + n] = mloss;

    // ---- block min -> atomicMin on float bits (all values > 0)
    float v = mloss;
#pragma unroll
    for (int o = 16; o > 0; o >>= 1) v = fminf(v, __shfl_xor_sync(0xffffffffu, v, o));
    __shared__ float wmin[8];
    if ((tid & 31) == 0) wmin[tid >> 5] = v;
    __syncthreads();
    if (tid == 0) {
        float bm = wmin[0];
#pragma unroll
        for (int w = 1; w < 8; w++) bm = fminf(bm, wmin[w]);
        atomicMin(&g_min[b], (unsigned int)__float_as_int(bm));
    }
}

__global__ __launch_bounds__(256) void weight_kernel(float* __restrict__ out) {
    const int b = blockIdx.x >> 3;
    const int i = (blockIdx.x & 7) * 256 + threadIdx.x;
    const float minl = __int_as_float((int)g_min[b]);
    float t = g_loss[b * NPTS + i] - minl;
    float w = 2.0f / (1.0f + expf(30.0f * t));   // 2*sigmoid(-30*t)
    out[b * NPTS + i] = (w > 0.6f) ? 1.0f : 0.0f;
}

extern "C" void kernel_launch(void* const* d_in, const int* in_sizes, int n_in,
                              void* d_out, int out_size) {
    const float* src = (const float*)d_in[0];
    const float* tgt = (const float*)d_in[1];
    float* out = (float*)d_out;

    const int smem = 2 * NPTS * (int)sizeof(float4);   // 64 KB
    cudaFuncSetAttribute(knn_loss_kernel, cudaFuncAttributeMaxDynamicSharedMemorySize, smem);

    init_min_kernel<<<1, 32>>>();
    knn_loss_kernel<<<BATCH * 8, 256, smem>>>(src, tgt);
    weight_kernel<<<BATCH * 8, 256>>>(out);
    dummy_kernel<<<1, 32>>>();   // shifts ncu's -s 5 capture onto knn_loss_kernel
}

// round 6
// speedup vs baseline: 1.7365x; 1.0395x over previous
#include <cuda_runtime.h>
#include <math.h>

#define BATCH 16
#define NPTS  2048
#define KNN   10

__device__ float4 g_s4[BATCH * NPTS];   // x, y, z, |p|^2
__device__ float4 g_t4[BATCH * NPTS];   // tx, ty, tz, 0
__device__ float g_loss[BATCH * NPTS];
__device__ unsigned int g_min[BATCH];   // float bits; positive => int-min == float-min

// Packed f32x2 helpers (per-lane IEEE fp32, identical rounding to scalar ops)
#define PACK2(out, lo, hi)  asm("mov.b64 %0, {%1, %2};" : "=l"(out) : "f"(lo), "f"(hi))
#define UNPACK2(lo, hi, in) asm("mov.b64 {%0, %1}, %2;" : "=f"(lo), "=f"(hi) : "l"(in))
#define MUL2(out, a, b)     asm("mul.rn.f32x2 %0, %1, %2;" : "=l"(out) : "l"(a), "l"(b))
#define ADD2(out, a, b)     asm("add.rn.f32x2 %0, %1, %2;" : "=l"(out) : "l"(a), "l"(b))
#define FMA2(out, a, b, c)  asm("fma.rn.f32x2 %0, %1, %2, %3;" : "=l"(out) : "l"(a), "l"(b), "l"(c))

typedef unsigned long long u64;

__device__ __forceinline__ void sort3(float& a, float& b, float& c) {
    float lo = fminf(a, b), hi = fmaxf(a, b);
    float l0 = fminf(lo, c);
    float l2 = fmaxf(hi, c);
    float l1 = fmaxf(lo, fminf(hi, c));
    a = l0; b = l1; c = l2;
}

// Compute packed keys for candidate pair (2u, 2u+1) of an 8-batch.
// key = ((sqn + sq_m) - 2*dot) + 1e-7 with dot = x*cx fma y*cy fma z*cz,
// identical rounding to the verified scalar version.
__device__ __forceinline__ void keys2(const float4 xy, const float4 zw,
                                      u64 xn2, u64 yn2, u64 zn2, u64 sqn2,
                                      u64 neg2, u64 eps2,
                                      float& k0, float& k1) {
    u64 cx2, cy2, cz2, cw2, t, s, d, k;
    PACK2(cx2, xy.x, xy.y); PACK2(cy2, xy.z, xy.w);
    PACK2(cz2, zw.x, zw.y); PACK2(cw2, zw.z, zw.w);
    MUL2(t, xn2, cx2);
    FMA2(t, yn2, cy2, t);
    FMA2(t, zn2, cz2, t);          // dot
    ADD2(s, sqn2, cw2);            // sqn + sq_m
    FMA2(d, t, neg2, s);           // d2 = s - 2*dot (one rounding, == scalar)
    ADD2(k, d, eps2);              // key = d2 + 1e-7
    UNPACK2(k0, k1, k);
}

// prep: transpose + squared norms into float4 arrays; also init g_min.
__global__ __launch_bounds__(256) void prep_kernel(const float* __restrict__ src,
                                                   const float* __restrict__ tgt) {
    const int b = blockIdx.x;
    const int tid = threadIdx.x;
    if (b == 0 && tid < BATCH) g_min[tid] = 0x7f800000u;  // +inf
    const float* sb = src + b * 3 * NPTS;
    const float* tb = tgt + b * 3 * NPTS;
    for (int i = tid; i < NPTS; i += 256) {
        float x = sb[i], y = sb[NPTS + i], z = sb[2 * NPTS + i];
        g_s4[b * NPTS + i] = make_float4(x, y, z, x * x + y * y + z * z);
        g_t4[b * NPTS + i] = make_float4(tb[i], tb[NPTS + i], tb[2 * NPTS + i], 0.0f);
    }
}

__global__ __launch_bounds__(256) void knn_loss_kernel() {
    __shared__ float4 pxy[NPTS / 2];   // (x0, x1, y0, y1) per candidate pair
    __shared__ float4 pzw[NPTS / 2];   // (z0, z1, sq0, sq1)

    const int b     = blockIdx.x >> 3;
    const int chunk = blockIdx.x & 7;
    const int tid   = threadIdx.x;

    const float4* s4b = g_s4 + b * NPTS;
    for (int i = tid; i < NPTS / 2; i += 256) {
        float4 a = s4b[2 * i], c = s4b[2 * i + 1];
        pxy[i] = make_float4(a.x, c.x, a.y, c.y);
        pzw[i] = make_float4(a.z, c.z, a.w, c.w);
    }
    __syncthreads();

    const float FINF = __int_as_float(0x7f800000);
    const int n = chunk * 256 + tid;

    const float4 pn = s4b[n];
    u64 xn2, yn2, zn2, sqn2, neg2, eps2;
    PACK2(xn2, pn.x, pn.x); PACK2(yn2, pn.y, pn.y);
    PACK2(zn2, pn.z, pn.z); PACK2(sqn2, pn.w, pn.w);
    { float m2 = -2.0f, ep = 1e-7f; PACK2(neg2, m2, m2); PACK2(eps2, ep, ep); }

    // ---- Pass 1: top-10 smallest key VALUES (key >= 0.1 mask), via min-max
    // lattice insert: kb sorted ascending; all slots independent (2 FMNMX each).
    float kb[KNN];
#pragma unroll
    for (int i = 0; i < KNN; i++) kb[i] = FINF;
    float thresh = FINF;

    for (int m0 = 0; m0 < NPTS; m0 += 8) {
        float key[8];
#pragma unroll
        for (int up = 0; up < 4; up++)
            keys2(pxy[(m0 >> 1) + up], pzw[(m0 >> 1) + up],
                  xn2, yn2, zn2, sqn2, neg2, eps2, key[2 * up], key[2 * up + 1]);
#pragma unroll
        for (int u = 0; u < 8; u++) {
            float c = key[u];
            if (c < thresh && c >= 0.1f) {
                float nk[KNN];
                nk[0] = fminf(kb[0], c);
#pragma unroll
                for (int s = 1; s < KNN; s++) nk[s] = fminf(kb[s], fmaxf(kb[s - 1], c));
#pragma unroll
                for (int s = 0; s < KNN; s++) kb[s] = nk[s];
                thresh = kb[KNN - 1];
            }
        }
    }

    // ---- Pass 2: recover the 10 indices (keys recomputed bit-identically;
    // collect candidates with key <= kb[9] in ascending index order == top_k
    // tie-break; neighbor order within the set is irrelevant downstream).
    int ib[KNN];
#pragma unroll
    for (int i = 0; i < KNN; i++) ib[i] = 0;
    int cnt = 0;

    for (int m0 = 0; m0 < NPTS; m0 += 8) {
        float key[8];
#pragma unroll
        for (int up = 0; up < 4; up++)
            keys2(pxy[(m0 >> 1) + up], pzw[(m0 >> 1) + up],
                  xn2, yn2, zn2, sqn2, neg2, eps2, key[2 * up], key[2 * up + 1]);
#pragma unroll
        for (int u = 0; u < 8; u++) {
            float c = key[u];
            if (c <= thresh && c >= 0.1f && cnt < KNN) {
#pragma unroll
                for (int s = KNN - 1; s > 0; --s) ib[s] = ib[s - 1];
                ib[0] = m0 + u;
                cnt++;
            }
        }
    }

    // ---- Phase 2: gather 10 neighbors (src & tgt) from global (L2-resident)
    const float4* t4b = g_t4 + b * NPTS;
    float nsx[KNN], nsy[KNN], nsz[KNN], ntx[KNN], nty[KNN], ntz[KNN];
#pragma unroll
    for (int i = 0; i < KNN; i++) {
        float4 cs = s4b[ib[i]];
        float4 ct = t4b[ib[i]];
        nsx[i] = cs.x; nsy[i] = cs.y; nsz[i] = cs.z;
        ntx[i] = ct.x; nty[i] = ct.y; ntz[i] = ct.z;
    }
    const float4 tn = t4b[n];
    const float xn = pn.x, yn = pn.y, zn = pn.z;
    const float xtn = tn.x, ytn = tn.y, ztn = tn.z;

    float ds0[KNN], dt0[KNN];
#pragma unroll
    for (int i = 0; i < KNN; i++) {
        float dx = xn - nsx[i], dy = yn - nsy[i], dz = zn - nsz[i];
        ds0[i] = dx * dx + dy * dy + dz * dz;
        float ex = xtn - ntx[i], ey = ytn - nty[i], ez = ztn - ntz[i];
        dt0[i] = ex * ex + ey * ey + ez * ez;
    }

    // ---- Phase 3: 45 pairs; keep 10 smallest losses via the same lattice
    // (unconditional; lb stays sorted ascending -> sum order matches ref).
    float lb[KNN];
#pragma unroll
    for (int i = 0; i < KNN; i++) lb[i] = FINF;

#pragma unroll
    for (int i = 0; i < KNN; i++) {
#pragma unroll
        for (int j = i + 1; j < KNN; j++) {
            float dx = nsx[i] - nsx[j], dy = nsy[i] - nsy[j], dz = nsz[i] - nsz[j];
            float bs = dx * dx + dy * dy + dz * dz;
            float l0 = ds0[i], l1 = bs, l2 = ds0[j];
            sort3(l0, l1, l2);

            float ex = ntx[i] - ntx[j], ey = nty[i] - nty[j], ez = ntz[i] - ntz[j];
            float bt = ex * ex + ey * ey + ez * ez;
            float m0 = dt0[i], m1 = bt, m2 = dt0[j];
            sort3(m0, m1, m2);
            m0 += 1e-6f; m1 += 1e-6f; m2 += 1e-6f;   // length_tgt = sort(tri) + EPS

            float e0 = l0 - m0, e1 = l1 - m1, e2 = l2 - m2;
            float num = e0 * e0 + e1 * e1 + e2 * e2;
            float s0 = l0 + m0, s1 = l1 + m1, s2 = l2 + m2;
            float den = s0 * s0 + s1 * s1 + s2 * s2;
            float ck = num / den;

            float nl[KNN];
            nl[0] = fminf(lb[0], ck);
#pragma unroll
            for (int s = 1; s < KNN; s++) nl[s] = fminf(lb[s], fmaxf(lb[s - 1], ck));
#pragma unroll
            for (int s = 0; s < KNN; s++) lb[s] = nl[s];
        }
    }

    float acc = 0.0f;
#pragma unroll
    for (int i = 0; i < KNN; i++) acc += sqrtf(lb[i] + 1e-6f);
    float mloss = acc / 10.0f;

    g_loss[b * NPTS + n] = mloss;

    // ---- block min -> atomicMin on float bits (all values > 0)
    float v = mloss;
#pragma unroll
    for (int o = 16; o > 0; o >>= 1) v = fminf(v, __shfl_xor_sync(0xffffffffu, v, o));
    __shared__ float wmin[8];
    if ((tid & 31) == 0) wmin[tid >> 5] = v;
    __syncthreads();
    if (tid == 0) {
        float bm = wmin[0];
#pragma unroll
        for (int w = 1; w < 8; w++) bm = fminf(bm, wmin[w]);
        atomicMin(&g_min[b], (unsigned int)__float_as_int(bm));
    }
}

__global__ __launch_bounds__(256) void weight_kernel(float* __restrict__ out) {
    const int b = blockIdx.x >> 3;
    const int i = (blockIdx.x & 7) * 256 + threadIdx.x;
    const float minl = __int_as_float((int)g_min[b]);
    float t = g_loss[b * NPTS + i] - minl;
    float w = 2.0f / (1.0f + expf(30.0f * t));   // 2*sigmoid(-30*t)
    out[b * NPTS + i] = (w > 0.6f) ? 1.0f : 0.0f;
}

extern "C" void kernel_launch(void* const* d_in, const int* in_sizes, int n_in,
                              void* d_out, int out_size) {
    const float* src = (const float*)d_in[0];
    const float* tgt = (const float*)d_in[1];
    float* out = (float*)d_out;

    prep_kernel<<<BATCH, 256>>>(src, tgt);
    knn_loss_kernel<<<BATCH * 8, 256>>>();
    weight_kernel<<<BATCH * 8, 256>>>(out);
}